// round 10
// baseline (speedup 1.0000x reference)
#include <cuda_runtime.h>
#include <math.h>

// Problem constants: B=2, T=8, N=65536, M=128, F=5, S=128
#define B_ 2
#define T_ 8
#define N_ 65536
#define M_ 128
#define F_ 5
#define S_ 128
#define GAMMA_ 1.1f

#define NTHREADS 256
#define NWARPS 8
#define CHUNK 4096                      // points per chunk (16/thread)
#define NCHUNK (N_ / CHUNK)             // 16
#define TOTALPTS (B_ * T_ * N_)         // 1,048,576

// SoA scratch for xy (predicate scan reads these coalesced).
__device__ __align__(16) float g_x[TOTALPTS];
__device__ __align__(16) float g_y[TOTALPTS];

// AoS->SoA transpose: 4 points (= 5 float4) per thread.
__global__ __launch_bounds__(NTHREADS)
void transpose_xy_kernel(const float4* __restrict__ pts4)
{
    const int i4 = blockIdx.x * NTHREADS + threadIdx.x;
    const float4 p0 = pts4[i4 * 5 + 0];
    const float4 p1 = pts4[i4 * 5 + 1];
    const float4 p2 = pts4[i4 * 5 + 2];
    const float4 p3 = pts4[i4 * 5 + 3];
    const float4 p4 = pts4[i4 * 5 + 4];
    ((float4*)g_x)[i4] = make_float4(p0.x, p1.y, p2.z, p3.w);
    ((float4*)g_y)[i4] = make_float4(p0.y, p1.z, p2.w, p4.x);
}

// ---- packed f32x2 helpers (per-lane exact .rn => bit-identical to scalar) ----
__device__ __forceinline__ unsigned long long pk2(float lo, float hi) {
    unsigned long long r;
    asm("mov.b64 %0, {%1, %2};" : "=l"(r) : "f"(lo), "f"(hi));
    return r;
}
__device__ __forceinline__ unsigned long long sub2(unsigned long long a,
                                                   unsigned long long b) {
    unsigned long long d;
    asm("sub.rn.f32x2 %0, %1, %2;" : "=l"(d) : "l"(a), "l"(b));
    return d;
}
__device__ __forceinline__ unsigned long long mul2(unsigned long long a,
                                                   unsigned long long b) {
    unsigned long long d;
    asm("mul.rn.f32x2 %0, %1, %2;" : "=l"(d) : "l"(a), "l"(b));
    return d;
}
__device__ __forceinline__ unsigned long long add2(unsigned long long a,
                                                   unsigned long long b) {
    unsigned long long d;
    asm("add.rn.f32x2 %0, %1, %2;" : "=l"(d) : "l"(a), "l"(b));
    return d;
}
__device__ __forceinline__ void unpk2(unsigned long long v, float& lo, float& hi) {
    asm("mov.b64 {%0, %1}, %2;" : "=f"(lo), "=f"(hi) : "l"(v));
}

__device__ __forceinline__ unsigned long long spread4(unsigned v)
{
    return (unsigned long long)(v & 0xFFu)
         | ((unsigned long long)(v & 0xFF00u)     << 8)
         | ((unsigned long long)(v & 0xFF0000u)   << 16)
         | ((unsigned long long)(v & 0xFF000000u) << 24);
}

// thr = largest float x with sqrtf(x) <= r  => (d2 <= thr) bit-identical to
// (sqrtf(d2) <= r); removes the per-point sqrt.
__device__ __forceinline__ float roi_setup(const float* __restrict__ roi,
                                           float& cx, float& cy)
{
    cx = roi[0];
    cy = roi[1];
    const float hl = __fmul_rn(roi[3], 0.5f);
    const float hw = __fmul_rn(roi[4], 0.5f);
    const float rr = __fmul_rn(
        sqrtf(__fadd_rn(__fmul_rn(hl, hl), __fmul_rn(hw, hw))), GAMMA_);
    float thr = __fmul_rn(rr, rr);
    while (sqrtf(thr) > rr) thr = __int_as_float(__float_as_int(thr) - 1);
    for (;;) {
        float nxt = __int_as_float(__float_as_int(thr) + 1);
        if (sqrtf(nxt) <= rr) thr = nxt; else break;
    }
    return thr;
}

// One CTA per (b, t, m). Pipelined chunk loop: mask -> scan -> BAR -> unpack
// -> (conditionally) issue next chunk's loads -> emit writes. One barrier per
// chunk. Emit writes x,y straight from the scan registers; only z,w,v are
// gathered from the AoS points.
__global__ __launch_bounds__(NTHREADS)
void voxel_pool_kernel(const float* __restrict__ pts,
                       const float* __restrict__ rois,
                       const int* __restrict__ vl,
                       float* __restrict__ out)
{
    const int gid = blockIdx.x;             // (b*T + t)*M + m
    const int m = gid & (M_ - 1);
    const int t = (gid >> 7) & (T_ - 1);
    const int b = gid >> 10;
    const int tid  = threadIdx.x;
    const int lane = tid & 31;
    const int wid  = tid >> 5;

    int use_t = t;
    if (t != 0 && vl[(b * T_ + t) * M_ + m] == 0) use_t = 0;

    const int slab = b * T_ + use_t;
    const float*  P  = pts + (size_t)slab * N_ * F_;
    const float4* X4 = (const float4*)(g_x + (size_t)slab * N_);
    const float4* Y4 = (const float4*)(g_y + (size_t)slab * N_);
    float* O = out + ((size_t)(b * M_ + m) * (T_ * S_) + (size_t)t * S_) * F_;

    __shared__ unsigned long long s_cnt[2][NWARPS];

    // Chunk-0 loads (independent of roi params).
    float4 xb[2][4], yb[2][4];
    #pragma unroll
    for (int g = 0; g < 4; g++) {
        xb[0][g] = X4[g * NTHREADS + tid];
        yb[0][g] = Y4[g * NTHREADS + tid];
    }

    // Roi setup, redundantly in every thread (overlaps the loads above).
    float cx, cy;
    const float thr = roi_setup(rois + ((size_t)slab * M_ + m) * 7, cx, cy);
    const unsigned long long cx2 = pk2(cx, cx);
    const unsigned long long cy2 = pk2(cy, cy);

    int total = 0;   // uniform across CTA
    #pragma unroll 1
    for (int c = 0; c < NCHUNK; c++) {
        const int cur = c & 1;

        // 16-bit match mask; bit g*4+k <-> point c*4096 + g*1024 + tid*4 + k.
        unsigned mask = 0;
        #pragma unroll
        for (int g = 0; g < 4; g++) {
            const float4 xv = xb[cur][g];
            const float4 yv = yb[cur][g];
            const unsigned long long d01 =
                add2(mul2(sub2(pk2(xv.x, xv.y), cx2), sub2(pk2(xv.x, xv.y), cx2)),
                     mul2(sub2(pk2(yv.x, yv.y), cy2), sub2(pk2(yv.x, yv.y), cy2)));
            const unsigned long long d23 =
                add2(mul2(sub2(pk2(xv.z, xv.w), cx2), sub2(pk2(xv.z, xv.w), cx2)),
                     mul2(sub2(pk2(yv.z, yv.w), cy2), sub2(pk2(yv.z, yv.w), cy2)));
            float d0, d1, d2, d3;
            unpk2(d01, d0, d1);
            unpk2(d23, d2, d3);
            mask |= (d0 <= thr ? 1u : 0u) << (g * 4 + 0);
            mask |= (d1 <= thr ? 1u : 0u) << (g * 4 + 1);
            mask |= (d2 <= thr ? 1u : 0u) << (g * 4 + 2);
            mask |= (d3 <= thr ? 1u : 0u) << (g * 4 + 3);
        }

        // Byte-packed per-group counts + warp scan.
        unsigned cp = 0;
        #pragma unroll
        for (int g = 0; g < 4; g++)
            cp |= (unsigned)__popc((mask >> (4 * g)) & 0xFu) << (8 * g);

        unsigned incl = cp;
        #pragma unroll
        for (int d = 1; d < 32; d <<= 1) {
            const unsigned v = __shfl_up_sync(0xFFFFFFFFu, incl, d);
            if (lane >= d) incl += v;
        }
        const unsigned wtot = __shfl_sync(0xFFFFFFFFu, incl, 31);
        const unsigned excl = incl - cp;

        if (lane == 0) s_cnt[cur][wid] = spread4(wtot);
        __syncthreads();   // single barrier per chunk (ping-pong buffers)

        unsigned long long tot64 = 0, bef64 = 0;
        #pragma unroll
        for (int w = 0; w < NWARPS; w++) {
            const unsigned long long v = s_cnt[cur][w];
            tot64 += v;
            if (w < wid) bef64 += v;
        }
        const unsigned a = (unsigned)tot64 + (unsigned)(tot64 >> 32);
        const int chunkTotal = (int)((a & 0xFFFFu) + (a >> 16));
        const int totalNew = total + chunkTotal;

        // Issue next chunk's loads now (hidden behind emit below). Only when
        // actually needed -- no speculative L2 traffic.
        if (totalNew < S_ && c + 1 < NCHUNK) {
            const int b4 = (c + 1) * (CHUNK / 4);
            #pragma unroll
            for (int g = 0; g < 4; g++) {
                xb[cur ^ 1][g] = X4[b4 + g * NTHREADS + tid];
                yb[cur ^ 1][g] = Y4[b4 + g * NTHREADS + tid];
            }
        }

        // Ordered emit of this thread's matches.
        if (mask) {
            int fp = 0;
            #pragma unroll
            for (int g = 0; g < 4; g++) {
                const int tj = (int)((tot64 >> (16 * g)) & 0xFFFFu);
                const int bj = (int)((bef64 >> (16 * g)) & 0xFFFFu);
                int r = total + fp + bj + (int)((excl >> (8 * g)) & 0xFFu);
                unsigned mj = (mask >> (4 * g)) & 0xFu;
                const float* xs = (const float*)&xb[cur][g];
                const float* ys = (const float*)&yb[cur][g];
                while (mj) {
                    const int k = __ffs(mj) - 1;
                    mj &= mj - 1;
                    if (r < S_) {
                        const int pt = c * CHUNK + g * (NTHREADS * 4) + tid * 4 + k;
                        const float* src = P + (size_t)pt * F_;
                        float* dst = O + r * F_;
                        dst[0] = xs[k];          // x from scan registers
                        dst[1] = ys[k];          // y from scan registers
                        dst[2] = src[2];         // z, l, w gathered (3 loads)
                        dst[3] = src[3];
                        dst[4] = src[4];
                    }
                    r++;
                }
                fp += tj;
            }
        }

        total = totalNew;
        if (total >= S_) break;   // uniform
    }

    // Zero-fill rows [written, S).
    const int written = (total < S_) ? total : S_;
    const int zfl = (S_ - written) * F_;
    for (int i = tid; i < zfl; i += NTHREADS) {
        O[written * F_ + i] = 0.0f;
    }
}

extern "C" void kernel_launch(void* const* d_in, const int* in_sizes, int n_in,
                              void* d_out, int out_size)
{
    const float* pts  = (const float*)d_in[0];  // [B,T,N,F] f32
    const float* rois = (const float*)d_in[1];  // [B,T,M,7] f32
    const int*   vl   = (const int*)d_in[2];    // [B,T,M]   i32
    float* out = (float*)d_out;                 // [B,M,T*S,F] f32

    (void)in_sizes; (void)n_in; (void)out_size;
    transpose_xy_kernel<<<TOTALPTS / 4 / NTHREADS, NTHREADS>>>((const float4*)pts);
    voxel_pool_kernel<<<B_ * T_ * M_, NTHREADS>>>(pts, rois, vl, out);
}

// round 12
// speedup vs baseline: 1.9721x; 1.9721x over previous
#include <cuda_runtime.h>
#include <math.h>

// Problem constants: B=2, T=8, N=65536, M=128, F=5, S=128
#define B_ 2
#define T_ 8
#define N_ 65536
#define M_ 128
#define F_ 5
#define S_ 128
#define GAMMA_ 1.1f

#define NTHREADS 256
#define NWARPS 8
#define SUBPTS 4096                 // points per sub-chunk (16/thread)
#define TAILSC 3                    // sub-chunks per tail iteration
#define NSLOTS (B_ * T_ * M_)       // 2048 output slots
#define TOTALPTS (B_ * T_ * N_)     // 1,048,576

// SoA scratch for xy + per-slot precomputed params + execution order.
__device__ __align__(16) float g_x[TOTALPTS];
__device__ __align__(16) float g_y[TOTALPTS];
__device__ float g_cx[NSLOTS];
__device__ float g_cy[NSLOTS];
__device__ float g_thr[NSLOTS];
__device__ int   g_slab[NSLOTS];
__device__ int   g_order[NSLOTS];
__device__ int   g_nfront, g_nback;

// AoS->SoA transpose: 4 points (= 5 float4) per thread. Thread 0 of block 0
// resets the ordering counters (stream-ordered before classify).
__global__ __launch_bounds__(NTHREADS)
void transpose_xy_kernel(const float4* __restrict__ pts4)
{
    if (blockIdx.x == 0 && threadIdx.x == 0) { g_nfront = 0; g_nback = 0; }
    const int i4 = blockIdx.x * NTHREADS + threadIdx.x;
    const float4 p0 = pts4[i4 * 5 + 0];
    const float4 p1 = pts4[i4 * 5 + 1];
    const float4 p2 = pts4[i4 * 5 + 2];
    const float4 p3 = pts4[i4 * 5 + 3];
    const float4 p4 = pts4[i4 * 5 + 4];
    ((float4*)g_x)[i4] = make_float4(p0.x, p1.y, p2.z, p3.w);
    ((float4*)g_y)[i4] = make_float4(p0.y, p1.z, p2.w, p4.x);
}

// thr = largest float x with sqrtf(x) <= r  => (d2 <= thr) bit-identical to
// (sqrtf(d2) <= r); removes the per-point sqrt.
__device__ __forceinline__ float roi_setup(const float* __restrict__ roi,
                                           float& cx, float& cy)
{
    cx = roi[0];
    cy = roi[1];
    const float hl = __fmul_rn(roi[3], 0.5f);
    const float hw = __fmul_rn(roi[4], 0.5f);
    const float rr = __fmul_rn(
        sqrtf(__fadd_rn(__fmul_rn(hl, hl), __fmul_rn(hw, hw))), GAMMA_);
    float thr = __fmul_rn(rr, rr);
    while (sqrtf(thr) > rr) thr = __int_as_float(__float_as_int(thr) - 1);
    for (;;) {
        float nxt = __int_as_float(__float_as_int(thr) + 1);
        if (sqrtf(nxt) <= rr) thr = nxt; else break;
    }
    return thr;
}

// Per-slot params + straggler-first ordering. Expected matches per scanned
// point ~ thr * exp(-|c|^2/2) / 2: low-score rois must scan deep, so they go
// to the FRONT of the execution queue and overlap the bulk. Ordering only
// affects scheduling; outputs are per-slot disjoint => deterministic result.
__global__ __launch_bounds__(NTHREADS)
void classify_kernel(const float* __restrict__ rois, const int* __restrict__ vl)
{
    const int slot = blockIdx.x * NTHREADS + threadIdx.x;   // (b*T + t)*M + m
    const int m = slot & (M_ - 1);
    const int t = (slot >> 7) & (T_ - 1);
    const int b = slot >> 10;

    int use_t = t;
    if (t != 0 && vl[slot] == 0) use_t = 0;
    const int slab = b * T_ + use_t;

    float cx, cy;
    const float thr = roi_setup(rois + ((size_t)slab * M_ + m) * 7, cx, cy);
    g_cx[slot] = cx;
    g_cy[slot] = cy;
    g_thr[slot] = thr;
    g_slab[slot] = slab;

    const float score = thr * __expf(-0.5f * (cx * cx + cy * cy));
    if (score < 0.02f) {
        const int p = atomicAdd(&g_nfront, 1);
        g_order[p] = slot;
    } else {
        const int p = atomicAdd(&g_nback, 1);
        g_order[NSLOTS - 1 - p] = slot;
    }
}

__device__ __forceinline__ unsigned long long spread4(unsigned v)
{
    return (unsigned long long)(v & 0xFFu)
         | ((unsigned long long)(v & 0xFF00u)     << 8)
         | ((unsigned long long)(v & 0xFF0000u)   << 16)
         | ((unsigned long long)(v & 0xFF000000u) << 24);
}

__device__ __forceinline__ unsigned predicate_mask(
    const float4* xv, const float4* yv, float cx, float cy, float thr)
{
    unsigned msk = 0;
    #pragma unroll
    for (int j = 0; j < 4; j++) {
        const float* xs = (const float*)&xv[j];
        const float* ys = (const float*)&yv[j];
        #pragma unroll
        for (int k = 0; k < 4; k++) {
            const float dx = __fsub_rn(xs[k], cx);
            const float dy = __fsub_rn(ys[k], cy);
            const float d2 = __fadd_rn(__fmul_rn(dx, dx), __fmul_rn(dy, dy));
            msk |= (d2 <= thr ? 1u : 0u) << (j * 4 + k);
        }
    }
    return msk;
}

__device__ __forceinline__ unsigned pack_counts(unsigned msk)
{
    unsigned cp = 0;
    #pragma unroll
    for (int j = 0; j < 4; j++)
        cp |= (unsigned)__popc((msk >> (4 * j)) & 0xFu) << (8 * j);
    return cp;
}

// Byte-packed inclusive warp scan; returns warp total, sets excl. Must be
// called CONVERGENTLY by all 32 lanes (warp-collective shfls inside).
__device__ __forceinline__ unsigned packed_scan(unsigned cp, int lane, unsigned& excl)
{
    unsigned incl = cp;
    #pragma unroll
    for (int d = 1; d < 32; d <<= 1) {
        const unsigned v = __shfl_up_sync(0xFFFFFFFFu, incl, d);
        if (lane >= d) incl += v;
    }
    excl = incl - cp;
    return __shfl_sync(0xFFFFFFFFu, incl, 31);
}

// Unpack per-warp counts, write this thread's matches in order.
__device__ __forceinline__ int write_subchunk(
    const unsigned long long* __restrict__ slotcnt, int wid, int tid,
    unsigned mask, unsigned excl, int total, int ptbase,
    const float* __restrict__ P, float* __restrict__ O)
{
    unsigned long long tot64 = 0, bef64 = 0;
    #pragma unroll
    for (int w = 0; w < NWARPS; w++) {
        const unsigned long long v = slotcnt[w];
        tot64 += v;
        if (w < wid) bef64 += v;
    }
    const unsigned a = (unsigned)tot64 + (unsigned)(tot64 >> 32);
    const int chunkTotal = (int)((a & 0xFFFFu) + (a >> 16));

    if (mask) {
        int fieldPrefix = 0;
        #pragma unroll
        for (int j = 0; j < 4; j++) {
            const int tj = (int)((tot64 >> (16 * j)) & 0xFFFFu);
            const int bj = (int)((bef64 >> (16 * j)) & 0xFFFFu);
            int r = total + fieldPrefix + bj + (int)((excl >> (8 * j)) & 0xFFu);
            unsigned mj = (mask >> (4 * j)) & 0xFu;
            while (mj) {
                const int k = __ffs(mj) - 1;
                mj &= mj - 1;
                if (r < S_) {
                    const int pt = ptbase + j * (NTHREADS * 4) + tid * 4 + k;
                    const float* src = P + (size_t)pt * F_;
                    float* dst = O + r * F_;
                    #pragma unroll
                    for (int f = 0; f < F_; f++) dst[f] = src[f];
                }
                r++;
            }
            fieldPrefix += tj;
        }
    }
    return chunkTotal;
}

// One CTA per output slot, executed in straggler-first order. Scan machinery
// identical to the proven R4 kernel: chunk 0, then 5 iterations x 3
// sub-chunks with batched prefetch and one barrier per iteration.
__global__ __launch_bounds__(NTHREADS)
void voxel_pool_kernel(const float* __restrict__ pts, float* __restrict__ out)
{
    const int slot = g_order[blockIdx.x];
    const int m = slot & (M_ - 1);
    const int t = (slot >> 7) & (T_ - 1);
    const int b = slot >> 10;
    const int tid  = threadIdx.x;
    const int lane = tid & 31;
    const int wid  = tid >> 5;

    const int slab = g_slab[slot];
    const float*  P  = pts + (size_t)slab * N_ * F_;
    const float4* X4 = (const float4*)(g_x + (size_t)slab * N_);
    const float4* Y4 = (const float4*)(g_y + (size_t)slab * N_);
    float* O = out + ((size_t)(b * M_ + m) * (T_ * S_) + (size_t)t * S_) * F_;

    __shared__ unsigned long long s_cnt[2][TAILSC][NWARPS];

    // Chunk-0 loads issued immediately.
    float4 xv0[4], yv0[4];
    #pragma unroll
    for (int j = 0; j < 4; j++) {
        xv0[j] = X4[j * NTHREADS + tid];
        yv0[j] = Y4[j * NTHREADS + tid];
    }

    const float cx  = g_cx[slot];
    const float cy  = g_cy[slot];
    const float thr = g_thr[slot];

    // ---- Chunk 0 (4096 points) ----  (all collectives convergent)
    const unsigned mask0 = predicate_mask(xv0, yv0, cx, cy, thr);
    unsigned excl0;
    const unsigned wt0 = packed_scan(pack_counts(mask0), lane, excl0);
    if (lane == 0) s_cnt[0][0][wid] = spread4(wt0);
    __syncthreads();

    int total = write_subchunk(s_cnt[0][0], wid, tid, mask0, excl0, 0, 0, P, O);

    // ---- Tail: 5 iterations x 3 sub-chunks (12288 pts, one barrier each) ----
    for (int it = 0; it < 5 && total < S_; it++) {
        const int buf = (it & 1) ^ 1;
        const int ptbase = SUBPTS + it * (TAILSC * SUBPTS);

        unsigned masks[TAILSC], excls[TAILSC];
        #pragma unroll
        for (int sc = 0; sc < TAILSC; sc++) {
            const int off4 = (ptbase + sc * SUBPTS) / 4;
            float4 xv[4], yv[4];
            #pragma unroll
            for (int j = 0; j < 4; j++) {
                xv[j] = X4[off4 + j * NTHREADS + tid];
                yv[j] = Y4[off4 + j * NTHREADS + tid];
            }
            masks[sc] = predicate_mask(xv, yv, cx, cy, thr);
            const unsigned wt = packed_scan(pack_counts(masks[sc]), lane, excls[sc]);
            if (lane == 0) s_cnt[buf][sc][wid] = spread4(wt);
        }
        __syncthreads();

        #pragma unroll
        for (int sc = 0; sc < TAILSC; sc++) {
            if (total < S_) {
                total += write_subchunk(s_cnt[buf][sc], wid, tid,
                                        masks[sc], excls[sc], total,
                                        ptbase + sc * SUBPTS, P, O);
            }
        }
    }

    // Zero-fill rows [written, S).
    const int written = (total < S_) ? total : S_;
    const int zfl = (S_ - written) * F_;
    for (int i = tid; i < zfl; i += NTHREADS) {
        O[written * F_ + i] = 0.0f;
    }
}

extern "C" void kernel_launch(void* const* d_in, const int* in_sizes, int n_in,
                              void* d_out, int out_size)
{
    const float* pts  = (const float*)d_in[0];  // [B,T,N,F] f32
    const float* rois = (const float*)d_in[1];  // [B,T,M,7] f32
    const int*   vl   = (const int*)d_in[2];    // [B,T,M]   i32
    float* out = (float*)d_out;                 // [B,M,T*S,F] f32

    (void)in_sizes; (void)n_in; (void)out_size;
    transpose_xy_kernel<<<TOTALPTS / 4 / NTHREADS, NTHREADS>>>((const float4*)pts);
    classify_kernel<<<NSLOTS / NTHREADS, NTHREADS>>>(rois, vl);
    voxel_pool_kernel<<<NSLOTS, NTHREADS>>>(pts, out);
}